// round 11
// baseline (speedup 1.0000x reference)
#include <cuda_runtime.h>
#include <cuda_bf16.h>
#include <cstdint>

#define NN      4096
#define DD      256
#define TWO_N   8192
#define NTILES  64
#define NBLK    2080        // NTILES*(NTILES+1)/2 upper-tri tiles
#define GRIDP   296         // persistent grid: 2 CTAs x 148 SMs
#define BMN     128
#define KC      64          // K-chunk (bf16) -> 128B rows, 16B-atom swizzle
#define NCHUNK  4           // DD / KC
#define NSTAGE  3
#define SCALE2  2.8853900817779268f   // (1/T) * log2(e)
#define LN2F    0.6931471805599453f

#define TILE_BYTES 16384                    // 128 rows x 64 bf16 x 2B
#define BUF_BYTES  (2 * TILE_BYTES)         // A, B per stage
#define DYN_BYTES  (NSTAGE * BUF_BYTES + 1024)

// z in bf16, PRE-SWIZZLED tile layout: [64 row-blocks][4 chunks][16KB tile]
__device__ __nv_bfloat16 g_zt[TWO_N * DD];
// scratch partials (base-2 domain)
__device__ float g_pm[TWO_N * NTILES];
__device__ float g_ps[TWO_N * NTILES];

// ---------------- helpers ----------------
__device__ __forceinline__ uint32_t smem_u32(const void* p) {
    uint32_t a;
    asm("{ .reg .u64 t; cvta.to.shared.u64 t, %1; cvt.u32.u64 %0, t; }" : "=r"(a) : "l"(p));
    return a;
}
#define SWZ(o) ((o) ^ (((o) >> 3) & 0x70))
#define MBAR_INIT(mb, c) asm volatile("mbarrier.init.shared.b64 [%0], %1;" :: "r"((uint32_t)(mb)), "r"((uint32_t)(c)) : "memory")
#define MBAR_EXPECT(mb, n) asm volatile("mbarrier.arrive.expect_tx.shared.b64 _, [%0], %1;" :: "r"((uint32_t)(mb)), "r"((uint32_t)(n)) : "memory")
#define BULK_G2S(dst, src, n, mb) \
    asm volatile("cp.async.bulk.shared::cluster.global.mbarrier::complete_tx::bytes [%0], [%1], %2, [%3];" \
        :: "r"((uint32_t)(dst)), "l"(src), "r"((uint32_t)(n)), "r"((uint32_t)(mb)) : "memory")
#define MBAR_WAIT(mb, ph) do {                                                   \
    uint32_t _m = (uint32_t)(mb), _p = (uint32_t)(ph), _d;                       \
    asm volatile("{\n\t.reg .pred p;\n\t"                                        \
        "mbarrier.try_wait.parity.acquire.cta.shared::cta.b64 p, [%1], %2;\n\t"  \
        "selp.b32 %0, 1, 0, p;\n\t}" : "=r"(_d) : "r"(_m), "r"(_p) : "memory");  \
    if (!_d) {                                                                   \
        asm volatile("{\n\t.reg .pred P1;\n\tWL_%=:\n\t"                         \
            "mbarrier.try_wait.parity.acquire.cta.shared::cta.b64 P1, [%0], %1, 0x989680;\n\t" \
            "@P1 bra.uni WD_%=;\n\tbra.uni WL_%=;\n\tWD_%=:\n\t}"                \
            :: "r"(_m), "r"(_p) : "memory");                                     \
    } } while (0)
#define LDM_X4(r, a) \
    asm volatile("ldmatrix.sync.aligned.m8n8.x4.shared.b16 {%0,%1,%2,%3}, [%4];" \
        : "=r"((r)[0]), "=r"((r)[1]), "=r"((r)[2]), "=r"((r)[3]) : "r"(a))
#define LDM_X2(r, a) \
    asm volatile("ldmatrix.sync.aligned.m8n8.x2.shared.b16 {%0,%1}, [%2];" \
        : "=r"((r)[0]), "=r"((r)[1]) : "r"(a))
#define MMA16816(c, a, b) \
    asm volatile("mma.sync.aligned.m16n8k16.row.col.f32.bf16.bf16.f32 " \
        "{%0,%1,%2,%3}, {%4,%5,%6,%7}, {%8,%9}, {%0,%1,%2,%3};" \
        : "+f"((c)[0]), "+f"((c)[1]), "+f"((c)[2]), "+f"((c)[3]) \
        : "r"((a)[0]), "r"((a)[1]), "r"((a)[2]), "r"((a)[3]), "r"((b)[0]), "r"((b)[1]))

__device__ __forceinline__ const float* zrow(const float* zi, const float* zj, int r) {
    return (r < NN) ? (zi + (long)r * DD) : (zj + (long)(r - NN) * DD);
}
__device__ __forceinline__ float ex2a(float u) {
    float r;
    asm("ex2.approx.f32 %0, %1;" : "=f"(r) : "f"(u));
    return r;
}
// triangular decode: tile index t -> (br, bc), bc >= br
__device__ __forceinline__ void decode_tile(int t, int& br, int& bc) {
    const float fN = (float)NTILES + 0.5f;
    int r = (int)(fN - sqrtf(fmaxf(fN * fN - 2.0f * (float)t, 0.0f)));
    if (r > NTILES - 1) r = NTILES - 1;
    if (r < 0) r = 0;
    while ((r + 1) * NTILES - ((r + 1) * r) / 2 <= t) r++;
    while (r * NTILES - (r * (r - 1)) / 2 > t) r--;
    br = r;
    bc = r + (t - (r * NTILES - (r * (r - 1)) / 2));
}

// ---- pre-pass: bf16-round z, write PRE-SWIZZLED tiles; also zero out[0] ----
__global__ void convert_kernel(const float* __restrict__ zi, const float* __restrict__ zj,
                               float* __restrict__ out) {
    if (blockIdx.x == 0 && threadIdx.x == 0) out[0] = 0.f;
    const long idx8 = ((long)blockIdx.x * blockDim.x + threadIdx.x) * 8;
    if (idx8 >= (long)TWO_N * DD) return;
    const int r  = (int)(idx8 >> 8);
    const int d0 = (int)(idx8 & 255);
    const float* src = zrow(zi, zj, r) + d0;
    float4 a = *(const float4*)(src);
    float4 b = *(const float4*)(src + 4);
    __nv_bfloat162 h[4];
    h[0] = __floats2bfloat162_rn(a.x, a.y);
    h[1] = __floats2bfloat162_rn(a.z, a.w);
    h[2] = __floats2bfloat162_rn(b.x, b.y);
    h[3] = __floats2bfloat162_rn(b.z, b.w);
    const int rb   = r >> 7;
    const int row  = r & 127;
    const int ch   = d0 >> 6;
    const int col0 = d0 & 63;
    char* tile = (char*)g_zt + ((long)(rb * NCHUNK + ch) << 14);
    const uint32_t o = (uint32_t)(row * 128 + col0 * 2);
    *(uint4*)(tile + SWZ(o)) = *(uint4*)h;
}

__global__ __launch_bounds__(256, 2)
void tile_kernel() {
    extern __shared__ char dynsmem[];
    __shared__ float s_row[BMN][4];
    __shared__ float s_col[BMN][2];
    __shared__ float s_red[8];
    __shared__ __align__(8) unsigned long long s_mbar[NSTAGE];

    const int tid  = threadIdx.x;
    const int wid  = tid >> 5;
    const int lane = tid & 31;
    const int wm   = (wid >> 2) * 64;
    const int wn   = (wid & 3) * 32;
    const int bid  = blockIdx.x;

    const uint32_t dynbase = (smem_u32(dynsmem) + 1023u) & ~1023u;
    uint32_t mbar[NSTAGE];
#pragma unroll
    for (int s = 0; s < NSTAGE; s++) mbar[s] = smem_u32(&s_mbar[s]);

    const int nt = (NBLK - bid + GRIDP - 1) / GRIDP;   // tiles for this CTA
    const int totalChunks = nt * NCHUNK;

    if (tid == 0) {
#pragma unroll
        for (int s = 0; s < NSTAGE; s++) MBAR_INIT(mbar[s], 1);
    }
    __syncthreads();

    // prologue: stage global chunks 0..2 (all inside first tile; NCHUNK=4 >= 3)
    if (tid == 0) {
        int br0, bc0;
        decode_tile(bid, br0, bc0);
        const char* Ag = (const char*)g_zt + ((long)(br0 * NCHUNK) << 14);
        const char* Bg = (const char*)g_zt + ((long)(bc0 * NCHUNK) << 14);
#pragma unroll
        for (int p = 0; p < NSTAGE; p++) {
            const uint32_t buf = dynbase + (uint32_t)p * BUF_BYTES;
            MBAR_EXPECT(mbar[p], BUF_BYTES);
            BULK_G2S(buf,              Ag + ((long)p << 14), TILE_BYTES, mbar[p]);
            BULK_G2S(buf + TILE_BYTES, Bg + ((long)p << 14), TILE_BYTES, mbar[p]);
        }
    }

    // per-lane ldmatrix constants
    const int rA  = lane & 15;
    const uint32_t kbA  = (uint32_t)((lane >> 4) * 16);
    const uint32_t xorA = (uint32_t)((rA & 7) << 4);
    const int rB  = lane & 7;
    const uint32_t kbB  = (uint32_t)(((lane >> 3) & 1) * 16);
    const uint32_t xorB = (uint32_t)(rB << 4);
    uint32_t ArowB[4], BrowB[4];
#pragma unroll
    for (int mi = 0; mi < 4; mi++) ArowB[mi] = (uint32_t)((wm + mi * 16 + rA) * 128);
#pragma unroll
    for (int ni = 0; ni < 4; ni++) BrowB[ni] = (uint32_t)((wn + ni * 8 + rB) * 128);

    const int lr = lane >> 2;
    const int lc = (lane & 3) * 2;

    int g = 0;   // global chunk counter (in-order consumption)
#pragma unroll 1
    for (int it = 0; it < nt; it++) {
        const int t = bid + it * GRIDP;
        int br, bc;
        decode_tile(t, br, bc);
        const bool isdiag = (br == bc);

        float acc[4][4][4];
#pragma unroll
        for (int mi = 0; mi < 4; mi++)
#pragma unroll
            for (int ni = 0; ni < 4; ni++)
#pragma unroll
                for (int q = 0; q < 4; q++) acc[mi][ni][q] = 0.f;

        // ---- consume this tile's 4 chunks; producer stages chunk g+3 ----
#pragma unroll 1
        for (int cc = 0; cc < NCHUNK; cc++, g++) {
            const int s = g % NSTAGE;
            const uint32_t buf = dynbase + (uint32_t)s * BUF_BYTES;
            MBAR_WAIT(mbar[s], (g / NSTAGE) & 1);

            const uint32_t At = buf;
            const uint32_t Bt = buf + TILE_BYTES;
#pragma unroll
            for (int ks = 0; ks < 4; ks++) {
                const uint32_t kA = ((uint32_t)(ks * 32) + kbA) ^ xorA;
                const uint32_t kB = ((uint32_t)(ks * 32) + kbB) ^ xorB;
                uint32_t af[4][4], bf[4][2];
#pragma unroll
                for (int mi = 0; mi < 4; mi++) LDM_X4(af[mi], At + ArowB[mi] + kA);
#pragma unroll
                for (int ni = 0; ni < 4; ni++) LDM_X2(bf[ni], Bt + BrowB[ni] + kB);
#pragma unroll
                for (int mi = 0; mi < 4; mi++)
#pragma unroll
                    for (int ni = 0; ni < 4; ni++)
                        MMA16816(acc[mi][ni], af[mi], bf[ni]);
            }
            __syncthreads();   // all warps done reading stage s
            const int gs = g + NSTAGE;
            if (gs < totalChunks && tid == 0) {
                const int it2 = gs >> 2;
                const int t2  = bid + it2 * GRIDP;
                int br2, bc2;
                decode_tile(t2, br2, bc2);
                const int ch = gs & 3;
                const uint32_t buf2 = dynbase + (uint32_t)(gs % NSTAGE) * BUF_BYTES;
                MBAR_EXPECT(mbar[gs % NSTAGE], BUF_BYTES);
                BULK_G2S(buf2,              (const char*)g_zt + ((long)(br2 * NCHUNK + ch) << 14), TILE_BYTES, mbar[gs % NSTAGE]);
                BULK_G2S(buf2 + TILE_BYTES, (const char*)g_zt + ((long)(bc2 * NCHUNK + ch) << 14), TILE_BYTES, mbar[gs % NSTAGE]);
            }
        }

        // ---- epilogue ----
        float m = -3.0e30f;
#pragma unroll
        for (int mi = 0; mi < 4; mi++)
#pragma unroll
            for (int ni = 0; ni < 4; ni++)
#pragma unroll
                for (int q = 0; q < 4; q++) {
                    float x = acc[mi][ni][q] * SCALE2;
                    if (isdiag) {
                        const int rloc = wm + mi * 16 + lr + ((q >> 1) << 3);
                        const int cloc = wn + ni * 8 + lc + (q & 1);
                        if (rloc == cloc) x = -3.0e30f;
                    }
                    acc[mi][ni][q] = x;
                    m = fmaxf(m, x);
                }
#pragma unroll
        for (int off = 16; off >= 1; off >>= 1)
            m = fmaxf(m, __shfl_xor_sync(0xffffffffu, m, off));
        if (lane == 0) s_red[wid] = m;
        __syncthreads();
        float Mt = s_red[0];
#pragma unroll
        for (int w = 1; w < 8; w++) Mt = fmaxf(Mt, s_red[w]);

        float rs[4][2], cs[4][2];
#pragma unroll
        for (int i = 0; i < 4; i++) { rs[i][0] = rs[i][1] = 0.f; cs[i][0] = cs[i][1] = 0.f; }
#pragma unroll
        for (int mi = 0; mi < 4; mi++)
#pragma unroll
            for (int ni = 0; ni < 4; ni++) {
                float e0 = ex2a(acc[mi][ni][0] - Mt);
                float e1 = ex2a(acc[mi][ni][1] - Mt);
                float e2 = ex2a(acc[mi][ni][2] - Mt);
                float e3 = ex2a(acc[mi][ni][3] - Mt);
                rs[mi][0] += e0 + e1;  rs[mi][1] += e2 + e3;
                cs[ni][0] += e0 + e2;  cs[ni][1] += e1 + e3;
            }
#pragma unroll
        for (int off = 1; off <= 2; off <<= 1)
#pragma unroll
            for (int mi = 0; mi < 4; mi++)
#pragma unroll
                for (int h = 0; h < 2; h++)
                    rs[mi][h] += __shfl_xor_sync(0xffffffffu, rs[mi][h], off);
#pragma unroll
        for (int off = 4; off <= 16; off <<= 1)
#pragma unroll
            for (int ni = 0; ni < 4; ni++)
#pragma unroll
                for (int p = 0; p < 2; p++)
                    cs[ni][p] += __shfl_xor_sync(0xffffffffu, cs[ni][p], off);

        if ((lane & 3) == 0) {
#pragma unroll
            for (int mi = 0; mi < 4; mi++)
#pragma unroll
                for (int h = 0; h < 2; h++)
                    s_row[wm + mi * 16 + lr + 8 * h][wid & 3] = rs[mi][h];
        }
        if (lane < 4) {
#pragma unroll
            for (int ni = 0; ni < 4; ni++)
#pragma unroll
                for (int p = 0; p < 2; p++)
                    s_col[wn + ni * 8 + 2 * lane + p][wid >> 2] = cs[ni][p];
        }
        __syncthreads();

        if (tid < BMN) {
            const float rsum = s_row[tid][0] + s_row[tid][1] + s_row[tid][2] + s_row[tid][3];
            const int gr = br * BMN + tid;
            g_pm[gr * NTILES + bc] = Mt;
            g_ps[gr * NTILES + bc] = rsum;
        } else if (!isdiag) {
            const int cc2 = tid - BMN;
            const float csum = s_col[cc2][0] + s_col[cc2][1];
            const int gc = bc * BMN + cc2;
            g_pm[gc * NTILES + br] = Mt;
            g_ps[gc * NTILES + br] = csum;
        }
        // chunk-loop syncthreads of the next tile order s_row/s_col/s_red reuse
    }
}

// One warp per row: merge 64 (m2, s) partials -> lse; positive dot (fp32);
// block-reduce 32 rows and atomically accumulate the mean into out[0].
__global__ __launch_bounds__(1024)
void finalize_kernel(const float* __restrict__ zi, const float* __restrict__ zj,
                     float* __restrict__ out) {
    __shared__ float sm[32];
    const int wwid = threadIdx.x >> 5;
    const int lane = threadIdx.x & 31;
    const int r = blockIdx.x * 32 + wwid;

    const float m0 = g_pm[r * NTILES + lane];
    const float m1 = g_pm[r * NTILES + 32 + lane];
    const float s0 = g_ps[r * NTILES + lane];
    const float s1 = g_ps[r * NTILES + 32 + lane];
    float m = fmaxf(m0, m1);
#pragma unroll
    for (int off = 16; off >= 1; off >>= 1)
        m = fmaxf(m, __shfl_xor_sync(0xffffffffu, m, off));
    float S = s0 * ex2a(m0 - m) + s1 * ex2a(m1 - m);
#pragma unroll
    for (int off = 16; off >= 1; off >>= 1)
        S += __shfl_xor_sync(0xffffffffu, S, off);

    const int p = (r < NN) ? r + NN : r - NN;
    const float* a = zrow(zi, zj, r);
    const float* b = zrow(zi, zj, p);
    float dot = 0.f;
#pragma unroll
    for (int q = 0; q < 2; q++) {
        const int k = lane * 8 + q * 4;
        float4 x = *(const float4*)(a + k);
        float4 y = *(const float4*)(b + k);
        dot += x.x * y.x + x.y * y.y + x.z * y.z + x.w * y.w;
    }
#pragma unroll
    for (int off = 16; off >= 1; off >>= 1)
        dot += __shfl_xor_sync(0xffffffffu, dot, off);

    if (lane == 0)
        sm[wwid] = (m + log2f(S)) * LN2F - dot * 2.0f;
    __syncthreads();
    if (wwid == 0) {
        float s = sm[lane];
#pragma unroll
        for (int off = 16; off >= 1; off >>= 1)
            s += __shfl_xor_sync(0xffffffffu, s, off);
        if (lane == 0) atomicAdd(out, s * (1.0f / (float)TWO_N));
    }
}

extern "C" void kernel_launch(void* const* d_in, const int* in_sizes, int n_in,
                              void* d_out, int out_size) {
    const float* zi = (const float*)d_in[0];
    const float* zj = (const float*)d_in[1];
    float* out = (float*)d_out;

    cudaStreamCaptureStatus st = cudaStreamCaptureStatusNone;
    cudaError_t qe = cudaStreamIsCapturing(0, &st);
    if (qe == cudaSuccess && st == cudaStreamCaptureStatusNone) {
        cudaFuncSetAttribute(tile_kernel,
                             cudaFuncAttributeMaxDynamicSharedMemorySize, DYN_BYTES);
    } else {
        cudaGetLastError();
    }

    convert_kernel<<<(TWO_N * DD / 8 + 255) / 256, 256>>>(zi, zj, out);
    tile_kernel<<<GRIDP, 256, DYN_BYTES>>>();
    finalize_kernel<<<TWO_N / 32, 1024>>>(zi, zj, out);
}

// round 12
// speedup vs baseline: 1.0452x; 1.0452x over previous
#include <cuda_runtime.h>
#include <cuda_bf16.h>
#include <cstdint>

#define NN      4096
#define DD      256
#define TWO_N   8192
#define NTILES  64
#define NBLK    2080        // NTILES*(NTILES+1)/2 upper-tri tiles
#define BMN     128
#define KC      64          // K-chunk (bf16) -> 128B rows, 16B-atom swizzle
#define NCHUNK  4           // DD / KC
#define NSTAGE  3
#define SCALE2  2.8853900817779268f   // (1/T) * log2(e)
#define LN2F    0.6931471805599453f

#define TILE_BYTES 16384                    // 128 rows x 64 bf16 x 2B
#define BUF_BYTES  (2 * TILE_BYTES)         // A, B per stage
#define DYN_BYTES  (NSTAGE * BUF_BYTES + 1024)

// z in bf16, PRE-SWIZZLED tile layout: [64 row-blocks][4 chunks][16KB tile]
__device__ __nv_bfloat16 g_zt[TWO_N * DD];
// scratch partials (base-2 domain)
__device__ float g_pm[TWO_N * NTILES];
__device__ float g_ps[TWO_N * NTILES];

// ---------------- helpers ----------------
__device__ __forceinline__ uint32_t smem_u32(const void* p) {
    uint32_t a;
    asm("{ .reg .u64 t; cvta.to.shared.u64 t, %1; cvt.u32.u64 %0, t; }" : "=r"(a) : "l"(p));
    return a;
}
#define SWZ(o) ((o) ^ (((o) >> 3) & 0x70))
#define MBAR_INIT(mb, c) asm volatile("mbarrier.init.shared.b64 [%0], %1;" :: "r"((uint32_t)(mb)), "r"((uint32_t)(c)) : "memory")
#define MBAR_EXPECT(mb, n) asm volatile("mbarrier.arrive.expect_tx.shared.b64 _, [%0], %1;" :: "r"((uint32_t)(mb)), "r"((uint32_t)(n)) : "memory")
#define BULK_G2S(dst, src, n, mb) \
    asm volatile("cp.async.bulk.shared::cluster.global.mbarrier::complete_tx::bytes [%0], [%1], %2, [%3];" \
        :: "r"((uint32_t)(dst)), "l"(src), "r"((uint32_t)(n)), "r"((uint32_t)(mb)) : "memory")
#define MBAR_WAIT(mb, ph) do {                                                   \
    uint32_t _m = (uint32_t)(mb), _p = (uint32_t)(ph), _d;                       \
    asm volatile("{\n\t.reg .pred p;\n\t"                                        \
        "mbarrier.try_wait.parity.acquire.cta.shared::cta.b64 p, [%1], %2;\n\t"  \
        "selp.b32 %0, 1, 0, p;\n\t}" : "=r"(_d) : "r"(_m), "r"(_p) : "memory");  \
    if (!_d) {                                                                   \
        asm volatile("{\n\t.reg .pred P1;\n\tWL_%=:\n\t"                         \
            "mbarrier.try_wait.parity.acquire.cta.shared::cta.b64 P1, [%0], %1, 0x989680;\n\t" \
            "@P1 bra.uni WD_%=;\n\tbra.uni WL_%=;\n\tWD_%=:\n\t}"                \
            :: "r"(_m), "r"(_p) : "memory");                                     \
    } } while (0)
#define LDM_X4(r, a) \
    asm volatile("ldmatrix.sync.aligned.m8n8.x4.shared.b16 {%0,%1,%2,%3}, [%4];" \
        : "=r"((r)[0]), "=r"((r)[1]), "=r"((r)[2]), "=r"((r)[3]) : "r"(a))
#define MMA16816(c, a, b0, b1) \
    asm volatile("mma.sync.aligned.m16n8k16.row.col.f32.bf16.bf16.f32 " \
        "{%0,%1,%2,%3}, {%4,%5,%6,%7}, {%8,%9}, {%0,%1,%2,%3};" \
        : "+f"((c)[0]), "+f"((c)[1]), "+f"((c)[2]), "+f"((c)[3]) \
        : "r"((a)[0]), "r"((a)[1]), "r"((a)[2]), "r"((a)[3]), "r"(b0), "r"(b1))

__device__ __forceinline__ const float* zrow(const float* zi, const float* zj, int r) {
    return (r < NN) ? (zi + (long)r * DD) : (zj + (long)(r - NN) * DD);
}
__device__ __forceinline__ float ex2a(float u) {
    float r;
    asm("ex2.approx.f32 %0, %1;" : "=f"(r) : "f"(u));
    return r;
}

// ---- pre-pass: bf16-round z, write PRE-SWIZZLED tiles; also zero out[0] ----
__global__ void convert_kernel(const float* __restrict__ zi, const float* __restrict__ zj,
                               float* __restrict__ out) {
    if (blockIdx.x == 0 && threadIdx.x == 0) out[0] = 0.f;
    const long idx8 = ((long)blockIdx.x * blockDim.x + threadIdx.x) * 8;
    if (idx8 >= (long)TWO_N * DD) return;
    const int r  = (int)(idx8 >> 8);
    const int d0 = (int)(idx8 & 255);
    const float* src = zrow(zi, zj, r) + d0;
    float4 a = *(const float4*)(src);
    float4 b = *(const float4*)(src + 4);
    __nv_bfloat162 h[4];
    h[0] = __floats2bfloat162_rn(a.x, a.y);
    h[1] = __floats2bfloat162_rn(a.z, a.w);
    h[2] = __floats2bfloat162_rn(b.x, b.y);
    h[3] = __floats2bfloat162_rn(b.z, b.w);
    const int rb   = r >> 7;
    const int row  = r & 127;
    const int ch   = d0 >> 6;
    const int col0 = d0 & 63;
    char* tile = (char*)g_zt + ((long)(rb * NCHUNK + ch) << 14);
    const uint32_t o = (uint32_t)(row * 128 + col0 * 2);
    *(uint4*)(tile + SWZ(o)) = *(uint4*)h;
}

__global__ __launch_bounds__(256, 2)
void tile_kernel() {
    // triangular decode: block t -> (br, bc), bc >= br
    const int t = blockIdx.x;
    const float fN = (float)NTILES + 0.5f;
    int br = (int)(fN - sqrtf(fmaxf(fN * fN - 2.0f * (float)t, 0.0f)));
    if (br > NTILES - 1) br = NTILES - 1;
    if (br < 0) br = 0;
    while ((br + 1) * NTILES - ((br + 1) * br) / 2 <= t) br++;
    while (br * NTILES - (br * (br - 1)) / 2 > t) br--;
    const int bc = br + (t - (br * NTILES - (br * (br - 1)) / 2));

    extern __shared__ char dynsmem[];
    __shared__ float s_row[BMN][4];
    __shared__ float s_col[BMN][2];
    __shared__ float s_red[8];
    __shared__ __align__(8) unsigned long long s_mbar[NSTAGE];

    const int tid  = threadIdx.x;
    const int wid  = tid >> 5;
    const int lane = tid & 31;
    const int wm   = (wid >> 2) * 64;
    const int wn   = (wid & 3) * 32;

    const uint32_t dynbase = (smem_u32(dynsmem) + 1023u) & ~1023u;
    uint32_t mbar[NSTAGE];
#pragma unroll
    for (int s = 0; s < NSTAGE; s++) mbar[s] = smem_u32(&s_mbar[s]);

    const char* Ag = (const char*)g_zt + ((long)(br * NCHUNK) << 14);
    const char* Bg = (const char*)g_zt + ((long)(bc * NCHUNK) << 14);

    if (tid == 0) {
#pragma unroll
        for (int s = 0; s < NSTAGE; s++) MBAR_INIT(mbar[s], 1);
    }
    __syncthreads();

    // prologue: stage chunks 0..2
    if (tid == 0) {
#pragma unroll
        for (int p = 0; p < NSTAGE; p++) {
            const uint32_t buf = dynbase + (uint32_t)p * BUF_BYTES;
            MBAR_EXPECT(mbar[p], BUF_BYTES);
            BULK_G2S(buf,              Ag + ((long)p << 14), TILE_BYTES, mbar[p]);
            BULK_G2S(buf + TILE_BYTES, Bg + ((long)p << 14), TILE_BYTES, mbar[p]);
        }
    }

    // per-lane ldmatrix constants (16B-atom swizzle; xor depends on lane&7 only)
    const int rA  = lane & 15;
    const uint32_t kbA  = (uint32_t)((lane >> 4) * 16);
    const uint32_t xorA = (uint32_t)((rA & 7) << 4);
    // B x4 pairing: lanes 0-7 -> (ni, kh0), 8-15 -> (ni, kh1),
    //               16-23 -> (ni+1, kh0), 24-31 -> (ni+1, kh1)
    const int rB4  = ((lane >> 4) & 1) * 8 + (lane & 7);
    const uint32_t kbB4 = (uint32_t)(((lane >> 3) & 1) * 16);
    const uint32_t xorB = (uint32_t)((lane & 7) << 4);
    uint32_t ArowB[4], BrowB4[2];
#pragma unroll
    for (int mi = 0; mi < 4; mi++) ArowB[mi] = (uint32_t)((wm + mi * 16 + rA) * 128);
#pragma unroll
    for (int p = 0; p < 2; p++) BrowB4[p] = (uint32_t)((wn + p * 16 + rB4) * 128);

    float acc[4][4][4];
#pragma unroll
    for (int mi = 0; mi < 4; mi++)
#pragma unroll
        for (int ni = 0; ni < 4; ni++)
#pragma unroll
            for (int q = 0; q < 4; q++) acc[mi][ni][q] = 0.f;

    // ---- mainloop: 3-stage bulk-copy pipeline, bf16 k16 steps ----
#pragma unroll 1
    for (int c = 0; c < NCHUNK; c++) {
        const int s = c % NSTAGE;
        const uint32_t buf = dynbase + (uint32_t)s * BUF_BYTES;
        MBAR_WAIT(mbar[s], (c / NSTAGE) & 1);

        const uint32_t At = buf;
        const uint32_t Bt = buf + TILE_BYTES;
#pragma unroll
        for (int ks = 0; ks < 4; ks++) {     // k = 16 bf16 per step = 32B
            const uint32_t kA = ((uint32_t)(ks * 32) + kbA) ^ xorA;
            const uint32_t kB = ((uint32_t)(ks * 32) + kbB4) ^ xorB;
            uint32_t af[4][4], bf[2][4];
#pragma unroll
            for (int mi = 0; mi < 4; mi++) LDM_X4(af[mi], At + ArowB[mi] + kA);
#pragma unroll
            for (int p = 0; p < 2; p++) LDM_X4(bf[p], Bt + BrowB4[p] + kB);
#pragma unroll
            for (int mi = 0; mi < 4; mi++)
#pragma unroll
                for (int ni = 0; ni < 4; ni++)
                    MMA16816(acc[mi][ni], af[mi], bf[ni >> 1][(ni & 1) * 2],
                             bf[ni >> 1][(ni & 1) * 2 + 1]);
        }
        __syncthreads();   // all warps done reading stage s
        if (c + NSTAGE < NCHUNK && tid == 0) {
            MBAR_EXPECT(mbar[s], BUF_BYTES);
            BULK_G2S(buf,              Ag + ((long)(c + NSTAGE) << 14), TILE_BYTES, mbar[s]);
            BULK_G2S(buf + TILE_BYTES, Bg + ((long)(c + NSTAGE) << 14), TILE_BYTES, mbar[s]);
        }
    }

    // ---- epilogue ----
    const bool isdiag = (br == bc);
    const int lr = lane >> 2;
    const int lc = (lane & 3) * 2;

    float m = -3.0e30f;
#pragma unroll
    for (int mi = 0; mi < 4; mi++)
#pragma unroll
        for (int ni = 0; ni < 4; ni++)
#pragma unroll
            for (int q = 0; q < 4; q++) {
                float x = acc[mi][ni][q] * SCALE2;
                if (isdiag) {
                    const int rloc = wm + mi * 16 + lr + ((q >> 1) << 3);
                    const int cloc = wn + ni * 8 + lc + (q & 1);
                    if (rloc == cloc) x = -3.0e30f;
                }
                acc[mi][ni][q] = x;
                m = fmaxf(m, x);
            }
#pragma unroll
    for (int off = 16; off >= 1; off >>= 1)
        m = fmaxf(m, __shfl_xor_sync(0xffffffffu, m, off));
    if (lane == 0) s_red[wid] = m;
    __syncthreads();
    float Mt = s_red[0];
#pragma unroll
    for (int w = 1; w < 8; w++) Mt = fmaxf(Mt, s_red[w]);

    float rs[4][2], cs[4][2];
#pragma unroll
    for (int i = 0; i < 4; i++) { rs[i][0] = rs[i][1] = 0.f; cs[i][0] = cs[i][1] = 0.f; }
#pragma unroll
    for (int mi = 0; mi < 4; mi++)
#pragma unroll
        for (int ni = 0; ni < 4; ni++) {
            float e0 = ex2a(acc[mi][ni][0] - Mt);
            float e1 = ex2a(acc[mi][ni][1] - Mt);
            float e2 = ex2a(acc[mi][ni][2] - Mt);
            float e3 = ex2a(acc[mi][ni][3] - Mt);
            rs[mi][0] += e0 + e1;  rs[mi][1] += e2 + e3;
            cs[ni][0] += e0 + e2;  cs[ni][1] += e1 + e3;
        }
#pragma unroll
    for (int off = 1; off <= 2; off <<= 1)
#pragma unroll
        for (int mi = 0; mi < 4; mi++)
#pragma unroll
            for (int h = 0; h < 2; h++)
                rs[mi][h] += __shfl_xor_sync(0xffffffffu, rs[mi][h], off);
#pragma unroll
    for (int off = 4; off <= 16; off <<= 1)
#pragma unroll
        for (int ni = 0; ni < 4; ni++)
#pragma unroll
            for (int p = 0; p < 2; p++)
                cs[ni][p] += __shfl_xor_sync(0xffffffffu, cs[ni][p], off);

    if ((lane & 3) == 0) {
#pragma unroll
        for (int mi = 0; mi < 4; mi++)
#pragma unroll
            for (int h = 0; h < 2; h++)
                s_row[wm + mi * 16 + lr + 8 * h][wid & 3] = rs[mi][h];
    }
    if (lane < 4) {
#pragma unroll
        for (int ni = 0; ni < 4; ni++)
#pragma unroll
            for (int p = 0; p < 2; p++)
                s_col[wn + ni * 8 + 2 * lane + p][wid >> 2] = cs[ni][p];
    }
    __syncthreads();

    if (tid < BMN) {
        const float rsum = s_row[tid][0] + s_row[tid][1] + s_row[tid][2] + s_row[tid][3];
        const int gr = br * BMN + tid;
        g_pm[gr * NTILES + bc] = Mt;
        g_ps[gr * NTILES + bc] = rsum;
    } else if (!isdiag) {
        const int cc = tid - BMN;
        const float csum = s_col[cc][0] + s_col[cc][1];
        const int gc = bc * BMN + cc;
        g_pm[gc * NTILES + br] = Mt;
        g_ps[gc * NTILES + br] = csum;
    }
}

// One warp per row: merge 64 (m2, s) partials -> lse; positive dot (fp32);
// block-reduce 32 rows and atomically accumulate the mean into out[0].
__global__ __launch_bounds__(1024)
void finalize_kernel(const float* __restrict__ zi, const float* __restrict__ zj,
                     float* __restrict__ out) {
    __shared__ float sm[32];
    const int wwid = threadIdx.x >> 5;
    const int lane = threadIdx.x & 31;
    const int r = blockIdx.x * 32 + wwid;

    const float m0 = g_pm[r * NTILES + lane];
    const float m1 = g_pm[r * NTILES + 32 + lane];
    const float s0 = g_ps[r * NTILES + lane];
    const float s1 = g_ps[r * NTILES + 32 + lane];
    float m = fmaxf(m0, m1);
#pragma unroll
    for (int off = 16; off >= 1; off >>= 1)
        m = fmaxf(m, __shfl_xor_sync(0xffffffffu, m, off));
    float S = s0 * ex2a(m0 - m) + s1 * ex2a(m1 - m);
#pragma unroll
    for (int off = 16; off >= 1; off >>= 1)
        S += __shfl_xor_sync(0xffffffffu, S, off);

    const int p = (r < NN) ? r + NN : r - NN;
    const float* a = zrow(zi, zj, r);
    const float* b = zrow(zi, zj, p);
    float dot = 0.f;
#pragma unroll
    for (int q = 0; q < 2; q++) {
        const int k = lane * 8 + q * 4;
        float4 x = *(const float4*)(a + k);
        float4 y = *(const float4*)(b + k);
        dot += x.x * y.x + x.y * y.y + x.z * y.z + x.w * y.w;
    }
#pragma unroll
    for (int off = 16; off >= 1; off >>= 1)
        dot += __shfl_xor_sync(0xffffffffu, dot, off);

    if (lane == 0)
        sm[wwid] = (m + log2f(S)) * LN2F - dot * 2.0f;
    __syncthreads();
    if (wwid == 0) {
        float s = sm[lane];
#pragma unroll
        for (int off = 16; off >= 1; off >>= 1)
            s += __shfl_xor_sync(0xffffffffu, s, off);
        if (lane == 0) atomicAdd(out, s * (1.0f / (float)TWO_N));
    }
}

extern "C" void kernel_launch(void* const* d_in, const int* in_sizes, int n_in,
                              void* d_out, int out_size) {
    const float* zi = (const float*)d_in[0];
    const float* zj = (const float*)d_in[1];
    float* out = (float*)d_out;

    cudaStreamCaptureStatus st = cudaStreamCaptureStatusNone;
    cudaError_t qe = cudaStreamIsCapturing(0, &st);
    if (qe == cudaSuccess && st == cudaStreamCaptureStatusNone) {
        cudaFuncSetAttribute(tile_kernel,
                             cudaFuncAttributeMaxDynamicSharedMemorySize, DYN_BYTES);
    } else {
        cudaGetLastError();
    }

    convert_kernel<<<(TWO_N * DD / 8 + 255) / 256, 256>>>(zi, zj, out);
    tile_kernel<<<NBLK, 256, DYN_BYTES>>>();
    finalize_kernel<<<TWO_N / 32, 1024>>>(zi, zj, out);
}